// round 2
// baseline (speedup 1.0000x reference)
#include <cuda_runtime.h>

#define B_      4
#define C_      128
#define N_      4096
#define HEADS_  4
#define DHEAD_  32
#define HID_    128
#define OQKV_   384

// Scratch (static device globals — no runtime allocation)
__device__ float g_mean[B_ * N_];
__device__ float g_rstd[B_ * N_];
__device__ float g_qkv [B_ * OQKV_ * N_];   // [b][o][n], q rows pre-scaled
__device__ float g_attn[B_ * HID_  * N_];   // [b][h*32+d][n]

// ---------------------------------------------------------------------------
// Kernel 1: per-position LayerNorm statistics over C=128 channels
// ---------------------------------------------------------------------------
__global__ void ln_stats_kernel(const float* __restrict__ x) {
    int idx = blockIdx.x * blockDim.x + threadIdx.x;   // b*N + n
    int b = idx >> 12;
    int n = idx & (N_ - 1);
    const float* xp = x + (size_t)b * C_ * N_ + n;
    float s = 0.f, s2 = 0.f;
#pragma unroll 8
    for (int c = 0; c < C_; c++) {
        float v = xp[(size_t)c * N_];
        s += v; s2 += v * v;
    }
    float m   = s  * (1.0f / C_);
    float var = s2 * (1.0f / C_) - m * m;
    g_mean[idx] = m;
    g_rstd[idx] = rsqrtf(var + 1e-5f);
}

// ---------------------------------------------------------------------------
// Tiled GEMM:  Y[b,o,n] = sum_c W[o,c] * Xn[b,c,n]   (+ optional LN / bias / qscale)
// Tile: 64 outputs x 64 positions, K chunked by 32. 256 threads, 4x4 frags.
// ---------------------------------------------------------------------------
template<int ODIM, bool LN, bool QSCALE, bool BIAS>
__global__ __launch_bounds__(256) void gemm_kernel(
    const float* __restrict__ Wm, const float* __restrict__ X,
    float* __restrict__ Y,
    const float* __restrict__ gamma, const float* __restrict__ beta,
    const float* __restrict__ bias)
{
    __shared__ float Ws[32][68];  // [kk][o]
    __shared__ float Xs[32][68];  // [kk][n]

    int b  = blockIdx.z;
    int n0 = blockIdx.x * 64;
    int o0 = blockIdx.y * 64;
    int tid = threadIdx.x;
    int tx = tid & 15, ty = tid >> 4;

    float acc[4][4] = {};
    const float* Xb = X + (size_t)b * C_ * N_;

    for (int k0 = 0; k0 < C_; k0 += 32) {
        { // load W tile, transposed into Ws[kk][ow]
            int ow  = tid >> 2;
            int kk0 = (tid & 3) * 8;
            const float* wp = Wm + (size_t)(o0 + ow) * C_ + k0 + kk0;
#pragma unroll
            for (int t = 0; t < 8; t++) Ws[kk0 + t][ow] = wp[t];
        }
        { // load X tile (LN applied on the fly for the QKV GEMM)
            int kk  = tid >> 3;
            int nx0 = (tid & 7) * 8;
            const float* xp = Xb + (size_t)(k0 + kk) * N_ + n0 + nx0;
            if (LN) {
                float ga = gamma[k0 + kk], be = beta[k0 + kk];
#pragma unroll
                for (int t = 0; t < 8; t++) {
                    int bn = b * N_ + n0 + nx0 + t;
                    Xs[kk][nx0 + t] = (xp[t] - g_mean[bn]) * g_rstd[bn] * ga + be;
                }
            } else {
#pragma unroll
                for (int t = 0; t < 8; t++) Xs[kk][nx0 + t] = xp[t];
            }
        }
        __syncthreads();
#pragma unroll
        for (int kk = 0; kk < 32; kk++) {
            float4 wv = *reinterpret_cast<const float4*>(&Ws[kk][ty * 4]);
            float4 xv = *reinterpret_cast<const float4*>(&Xs[kk][tx * 4]);
            float wa[4] = {wv.x, wv.y, wv.z, wv.w};
            float xa[4] = {xv.x, xv.y, xv.z, xv.w};
#pragma unroll
            for (int r = 0; r < 4; r++)
#pragma unroll
                for (int c = 0; c < 4; c++)
                    acc[r][c] += wa[r] * xa[c];
        }
        __syncthreads();
    }

    const float qscale = 0.17677669529663687f;  // 32^-0.5
#pragma unroll
    for (int r = 0; r < 4; r++) {
        int o = o0 + ty * 4 + r;
        float extra = BIAS ? bias[o] : 0.f;
        float mult  = (QSCALE && o < HID_) ? qscale : 1.f;
        float* yp = Y + ((size_t)b * ODIM + o) * N_ + n0 + tx * 4;
#pragma unroll
        for (int c = 0; c < 4; c++) yp[c] = acc[r][c] * mult + extra;
    }
}

// ---------------------------------------------------------------------------
// Kernel 3: flash attention, one (b,h,i-tile) per block.
// i-tile = 64 rows, j-tile = 64, d = 32. Online softmax.
// ---------------------------------------------------------------------------
__global__ __launch_bounds__(256) void attn_kernel() {
    __shared__ float Qs[32][68];   // [d][i]
    __shared__ float Ks[32][68];   // [d][j]
    __shared__ float Vs[64][33];   // [j][d]
    __shared__ float Ps[64][68];   // [i][j]; reused as [i][d] for output
    __shared__ float m_s[64], l_s[64], a_s[64];

    int bh = blockIdx.y;
    int b = bh >> 2, h = bh & 3;
    int i0 = blockIdx.x * 64;
    int tid = threadIdx.x;
    int tx = tid & 15, ty = tid >> 4;

    const float* qb = g_qkv + ((size_t)(b * OQKV_) +            h * DHEAD_) * N_;
    const float* kb = g_qkv + ((size_t)(b * OQKV_) + HID_     + h * DHEAD_) * N_;
    const float* vb = g_qkv + ((size_t)(b * OQKV_) + 2 * HID_ + h * DHEAD_) * N_;

#pragma unroll
    for (int t = 0; t < 8; t++) {
        int idx = tid + t * 256;
        int d = idx >> 6, i = idx & 63;
        Qs[d][i] = qb[(size_t)d * N_ + i0 + i];
    }
    if (tid < 64) { m_s[tid] = -1e30f; l_s[tid] = 0.f; }
    float o[4][2] = {};
    __syncthreads();

    for (int j0 = 0; j0 < N_; j0 += 64) {
#pragma unroll
        for (int t = 0; t < 8; t++) {
            int idx = tid + t * 256;
            int d = idx >> 6, j = idx & 63;
            Ks[d][j] = kb[(size_t)d * N_ + j0 + j];
            Vs[j][d] = vb[(size_t)d * N_ + j0 + j];
        }
        __syncthreads();

        // S = Q^T K on the 64x64 tile (4x4 per thread)
        float s[4][4] = {};
#pragma unroll
        for (int d = 0; d < 32; d++) {
            float4 qv = *reinterpret_cast<const float4*>(&Qs[d][ty * 4]);
            float4 kv = *reinterpret_cast<const float4*>(&Ks[d][tx * 4]);
            float qa[4] = {qv.x, qv.y, qv.z, qv.w};
            float ka[4] = {kv.x, kv.y, kv.z, kv.w};
#pragma unroll
            for (int r = 0; r < 4; r++)
#pragma unroll
                for (int c = 0; c < 4; c++)
                    s[r][c] += qa[r] * ka[c];
        }

        // online softmax: row reductions across the 16 tx lanes (width-16 xor)
        float m_old[4], m_new[4], rs[4];
#pragma unroll
        for (int r = 0; r < 4; r++) {
            int row = ty * 4 + r;
            m_old[r] = m_s[row];
            float rm = fmaxf(fmaxf(s[r][0], s[r][1]), fmaxf(s[r][2], s[r][3]));
#pragma unroll
            for (int msk = 8; msk >= 1; msk >>= 1)
                rm = fmaxf(rm, __shfl_xor_sync(0xffffffffu, rm, msk, 16));
            m_new[r] = fmaxf(m_old[r], rm);
            float ps = 0.f;
#pragma unroll
            for (int c = 0; c < 4; c++) {
                s[r][c] = __expf(s[r][c] - m_new[r]);
                ps += s[r][c];
            }
#pragma unroll
            for (int msk = 8; msk >= 1; msk >>= 1)
                ps += __shfl_xor_sync(0xffffffffu, ps, msk, 16);
            rs[r] = ps;
        }
        if (tx == 0) {
#pragma unroll
            for (int r = 0; r < 4; r++) {
                int row = ty * 4 + r;
                float alpha = __expf(m_old[r] - m_new[r]);
                m_s[row] = m_new[r];
                l_s[row] = l_s[row] * alpha + rs[r];
                a_s[row] = alpha;
            }
        }
#pragma unroll
        for (int r = 0; r < 4; r++) {
            float4 pv = make_float4(s[r][0], s[r][1], s[r][2], s[r][3]);
            *reinterpret_cast<float4*>(&Ps[ty * 4 + r][tx * 4]) = pv;
        }
        __syncthreads();

        // rescale O, accumulate P @ V^T  (O frag: 4 rows x 2 d per thread)
#pragma unroll
        for (int r = 0; r < 4; r++) {
            float alpha = a_s[ty * 4 + r];
            o[r][0] *= alpha; o[r][1] *= alpha;
        }
#pragma unroll 4
        for (int j = 0; j < 64; j++) {
            float vv0 = Vs[j][tx * 2], vv1 = Vs[j][tx * 2 + 1];
#pragma unroll
            for (int r = 0; r < 4; r++) {
                float p = Ps[ty * 4 + r][j];
                o[r][0] += p * vv0;
                o[r][1] += p * vv1;
            }
        }
        __syncthreads();
    }

    // finalize: divide by l, transpose through smem, coalesced store
#pragma unroll
    for (int r = 0; r < 4; r++) {
        float inv = 1.0f / l_s[ty * 4 + r];
        Ps[ty * 4 + r][tx * 2]     = o[r][0] * inv;
        Ps[ty * 4 + r][tx * 2 + 1] = o[r][1] * inv;
    }
    __syncthreads();
    float* ob = g_attn + ((size_t)b * HID_ + h * DHEAD_) * N_ + i0;
    {
        int i  = tid & 63;
        int d0 = tid >> 6;
#pragma unroll
        for (int t = 0; t < 8; t++) {
            int d = d0 + t * 4;
            ob[(size_t)d * N_ + i] = Ps[i][d];
        }
    }
}

// ---------------------------------------------------------------------------
extern "C" void kernel_launch(void* const* d_in, const int* in_sizes, int n_in,
                              void* d_out, int out_size) {
    const float* x     = (const float*)d_in[0];
    const float* g     = (const float*)d_in[1];
    const float* beta  = (const float*)d_in[2];
    const float* w_qkv = (const float*)d_in[3];
    const float* w_out = (const float*)d_in[4];
    const float* b_out = (const float*)d_in[5];
    float* out = (float*)d_out;

    float* qkv_ptr;  cudaGetSymbolAddress((void**)&qkv_ptr,  g_qkv);
    float* attn_ptr; cudaGetSymbolAddress((void**)&attn_ptr, g_attn);

    ln_stats_kernel<<<(B_ * N_) / 256, 256>>>(x);

    dim3 g2(N_ / 64, OQKV_ / 64, B_);
    gemm_kernel<OQKV_, true, true, false><<<g2, 256>>>(w_qkv, x, qkv_ptr, g, beta, nullptr);

    dim3 g3(N_ / 64, B_ * HEADS_);
    attn_kernel<<<g3, 256>>>();

    dim3 g4(N_ / 64, HID_ / 64, B_);
    gemm_kernel<HID_, false, false, true><<<g4, 256>>>(w_out, attn_ptr, out, nullptr, nullptr, b_out);
}

// round 3
// speedup vs baseline: 2.3851x; 2.3851x over previous
#include <cuda_runtime.h>
#include <cuda_fp16.h>

#define B_      4
#define C_      128
#define N_      4096
#define HEADS_  4
#define DHEAD_  32
#define HID_    128
#define OQKV_   384

// Scratch (static device globals — no runtime allocation)
__device__ float g_mean[B_ * N_];
__device__ float g_rstd[B_ * N_];
__device__ float g_qkv [B_ * OQKV_ * N_];   // [b][o][n], q rows pre-scaled
__device__ float g_attn[B_ * HID_  * N_];   // [b][h*32+d][n]

// ---------------------------------------------------------------------------
// Kernel 1: per-position LayerNorm statistics over C=128 channels
// ---------------------------------------------------------------------------
__global__ void ln_stats_kernel(const float* __restrict__ x) {
    int idx = blockIdx.x * blockDim.x + threadIdx.x;   // b*N + n
    int b = idx >> 12;
    int n = idx & (N_ - 1);
    const float* xp = x + (size_t)b * C_ * N_ + n;
    float s = 0.f, s2 = 0.f;
#pragma unroll 8
    for (int c = 0; c < C_; c++) {
        float v = xp[(size_t)c * N_];
        s += v; s2 += v * v;
    }
    float m   = s  * (1.0f / C_);
    float var = s2 * (1.0f / C_) - m * m;
    g_mean[idx] = m;
    g_rstd[idx] = rsqrtf(var + 1e-5f);
}

// ---------------------------------------------------------------------------
// Tiled GEMM:  Y[b,o,n] = sum_c W[o,c] * Xn[b,c,n]   (+ optional LN / bias / qscale)
// ---------------------------------------------------------------------------
template<int ODIM, bool LN, bool QSCALE, bool BIAS>
__global__ __launch_bounds__(256) void gemm_kernel(
    const float* __restrict__ Wm, const float* __restrict__ X,
    float* __restrict__ Y,
    const float* __restrict__ gamma, const float* __restrict__ beta,
    const float* __restrict__ bias)
{
    __shared__ float Ws[32][68];
    __shared__ float Xs[32][68];

    int b  = blockIdx.z;
    int n0 = blockIdx.x * 64;
    int o0 = blockIdx.y * 64;
    int tid = threadIdx.x;
    int tx = tid & 15, ty = tid >> 4;

    float acc[4][4] = {};
    const float* Xb = X + (size_t)b * C_ * N_;

    for (int k0 = 0; k0 < C_; k0 += 32) {
        {
            int ow  = tid >> 2;
            int kk0 = (tid & 3) * 8;
            const float* wp = Wm + (size_t)(o0 + ow) * C_ + k0 + kk0;
#pragma unroll
            for (int t = 0; t < 8; t++) Ws[kk0 + t][ow] = wp[t];
        }
        {
            int kk  = tid >> 3;
            int nx0 = (tid & 7) * 8;
            const float* xp = Xb + (size_t)(k0 + kk) * N_ + n0 + nx0;
            if (LN) {
                float ga = gamma[k0 + kk], be = beta[k0 + kk];
#pragma unroll
                for (int t = 0; t < 8; t++) {
                    int bn = b * N_ + n0 + nx0 + t;
                    Xs[kk][nx0 + t] = (xp[t] - g_mean[bn]) * g_rstd[bn] * ga + be;
                }
            } else {
#pragma unroll
                for (int t = 0; t < 8; t++) Xs[kk][nx0 + t] = xp[t];
            }
        }
        __syncthreads();
#pragma unroll
        for (int kk = 0; kk < 32; kk++) {
            float4 wv = *reinterpret_cast<const float4*>(&Ws[kk][ty * 4]);
            float4 xv = *reinterpret_cast<const float4*>(&Xs[kk][tx * 4]);
            float wa[4] = {wv.x, wv.y, wv.z, wv.w};
            float xa[4] = {xv.x, xv.y, xv.z, xv.w};
#pragma unroll
            for (int r = 0; r < 4; r++)
#pragma unroll
                for (int c = 0; c < 4; c++)
                    acc[r][c] += wa[r] * xa[c];
        }
        __syncthreads();
    }

    const float qscale = 0.17677669529663687f;  // 32^-0.5
#pragma unroll
    for (int r = 0; r < 4; r++) {
        int o = o0 + ty * 4 + r;
        float extra = BIAS ? bias[o] : 0.f;
        float mult  = (QSCALE && o < HID_) ? qscale : 1.f;
        float* yp = Y + ((size_t)b * ODIM + o) * N_ + n0 + tx * 4;
#pragma unroll
        for (int c = 0; c < 4; c++) yp[c] = acc[r][c] * mult + extra;
    }
}

// ---------------------------------------------------------------------------
// Flash attention on tensor cores (mma.sync m16n8k16 fp16, fp32 accum).
// i-tile = 128 rows (8 warps x 16), j-tile = 64. Online softmax in registers.
// Precision: S uses hi/lo-split Q,K (3 MMAs, ~fp32-exact); P plain fp16;
// V hi/lo split (2 MMAs).
// ---------------------------------------------------------------------------
__device__ __forceinline__ void mma16816(float* c, const unsigned* a,
                                         unsigned b0, unsigned b1) {
    asm volatile(
        "mma.sync.aligned.m16n8k16.row.col.f32.f16.f16.f32 "
        "{%0,%1,%2,%3}, {%4,%5,%6,%7}, {%8,%9}, {%0,%1,%2,%3};\n"
        : "+f"(c[0]), "+f"(c[1]), "+f"(c[2]), "+f"(c[3])
        : "r"(a[0]), "r"(a[1]), "r"(a[2]), "r"(a[3]), "r"(b0), "r"(b1));
}

__device__ __forceinline__ unsigned pack_h2(float x, float y) {
    __half2 h = __floats2half2_rn(x, y);   // x -> low, y -> high
    return *reinterpret_cast<unsigned*>(&h);
}
__device__ __forceinline__ void split_hl(float x, __half& h, __half& l) {
    h = __float2half_rn(x);
    l = __float2half_rn(x - __half2float(h));
}

#define KPITCH 40   // halves per row of K tiles [j][d]
#define VPITCH 72   // halves per row of V tiles [d][j]
#define SM_KH  0
#define SM_KL  2560
#define SM_VH  5120
#define SM_VL  7424
#define SM_HALVES 10240
#define QPITCH 33   // floats, for Q staging / O epilogue

__global__ __launch_bounds__(256) void attn_mma_kernel() {
    __shared__ __align__(16) __half SM[SM_HALVES];
    float* SMf = reinterpret_cast<float*>(SM);

    int bh = blockIdx.y;
    int b = bh >> 2, h = bh & 3;
    int i0 = blockIdx.x * 128;
    int tid  = threadIdx.x;
    int wid  = tid >> 5;
    int lane = tid & 31;
    int lq   = lane >> 2;          // lane/4
    int lr   = lane & 3;           // lane%4

    const float* qb = g_qkv + ((size_t)(b * OQKV_) +            h * DHEAD_) * N_;
    const float* kb = g_qkv + ((size_t)(b * OQKV_) + HID_     + h * DHEAD_) * N_;
    const float* vb = g_qkv + ((size_t)(b * OQKV_) + 2 * HID_ + h * DHEAD_) * N_;

    // ---- Stage Q (fp32) into smem: Qf[i][d], i=0..127, d=0..31 -------------
#pragma unroll
    for (int t = 0; t < 16; t++) {
        int idx = tid + t * 256;            // 4096 elements
        int d = idx >> 7, i = idx & 127;
        SMf[i * QPITCH + d] = qb[(size_t)d * N_ + i0 + i];
    }
    __syncthreads();

    // ---- Build Q fragments (hi/lo) for this warp's 16 rows -----------------
    unsigned aQh[2][4], aQl[2][4];
    {
        int r0 = wid * 16 + lq;
#pragma unroll
        for (int kt = 0; kt < 2; kt++) {
            int d0 = kt * 16 + lr * 2;
#pragma unroll
            for (int f = 0; f < 4; f++) {
                int r = r0 + ((f & 1) ? 8 : 0);
                int d = d0 + ((f & 2) ? 8 : 0);
                float x0 = SMf[r * QPITCH + d];
                float x1 = SMf[r * QPITCH + d + 1];
                __half h0, l0, h1, l1;
                split_hl(x0, h0, l0);
                split_hl(x1, h1, l1);
                __half2 hh = __halves2half2(h0, h1);
                __half2 ll = __halves2half2(l0, l1);
                aQh[kt][f] = *reinterpret_cast<unsigned*>(&hh);
                aQl[kt][f] = *reinterpret_cast<unsigned*>(&ll);
            }
        }
    }
    __syncthreads();

    float s[8][4];
    float o[4][4] = {};
    float m0 = -1e30f, m1 = -1e30f, l0 = 0.f, l1 = 0.f;
    const unsigned FULL = 0xffffffffu;

    for (int j0 = 0; j0 < N_; j0 += 64) {
        // ---- Load K/V tile, convert fp32 -> hi/lo halves --------------------
#pragma unroll
        for (int t = 0; t < 8; t++) {
            int idx = tid + t * 256;        // 2048 elements
            int d = idx >> 6, j = idx & 63;
            float kv = kb[(size_t)d * N_ + j0 + j];
            float vv = vb[(size_t)d * N_ + j0 + j];
            __half kh, kl, vh, vl;
            split_hl(kv, kh, kl);
            split_hl(vv, vh, vl);
            SM[SM_KH + j * KPITCH + d] = kh;
            SM[SM_KL + j * KPITCH + d] = kl;
            SM[SM_VH + d * VPITCH + j] = vh;
            SM[SM_VL + d * VPITCH + j] = vl;
        }
        __syncthreads();

        // ---- S = Q^T K (16x64 per warp), hi/lo compensated ------------------
#pragma unroll
        for (int nt = 0; nt < 8; nt++) {
            s[nt][0] = s[nt][1] = s[nt][2] = s[nt][3] = 0.f;
        }
#pragma unroll
        for (int kt = 0; kt < 2; kt++) {
            int dbase = kt * 16 + lr * 2;
#pragma unroll
            for (int nt = 0; nt < 8; nt++) {
                int jrow = nt * 8 + lq;
                unsigned bh0 = *reinterpret_cast<const unsigned*>(&SM[SM_KH + jrow * KPITCH + dbase]);
                unsigned bh1 = *reinterpret_cast<const unsigned*>(&SM[SM_KH + jrow * KPITCH + dbase + 8]);
                unsigned bl0 = *reinterpret_cast<const unsigned*>(&SM[SM_KL + jrow * KPITCH + dbase]);
                unsigned bl1 = *reinterpret_cast<const unsigned*>(&SM[SM_KL + jrow * KPITCH + dbase + 8]);
                mma16816(s[nt], aQh[kt], bh0, bh1);
                mma16816(s[nt], aQh[kt], bl0, bl1);
                mma16816(s[nt], aQl[kt], bh0, bh1);
            }
        }

        // ---- Online softmax (rows r0=lane/4, r1=r0+8 of warp strip) ---------
        float mx0 = -1e30f, mx1 = -1e30f;
#pragma unroll
        for (int nt = 0; nt < 8; nt++) {
            mx0 = fmaxf(mx0, fmaxf(s[nt][0], s[nt][1]));
            mx1 = fmaxf(mx1, fmaxf(s[nt][2], s[nt][3]));
        }
        mx0 = fmaxf(mx0, __shfl_xor_sync(FULL, mx0, 1));
        mx0 = fmaxf(mx0, __shfl_xor_sync(FULL, mx0, 2));
        mx1 = fmaxf(mx1, __shfl_xor_sync(FULL, mx1, 1));
        mx1 = fmaxf(mx1, __shfl_xor_sync(FULL, mx1, 2));
        float mn0 = fmaxf(m0, mx0), mn1 = fmaxf(m1, mx1);
        float al0 = __expf(m0 - mn0), al1 = __expf(m1 - mn1);
        m0 = mn0; m1 = mn1;

        float sum0 = 0.f, sum1 = 0.f;
#pragma unroll
        for (int nt = 0; nt < 8; nt++) {
            s[nt][0] = __expf(s[nt][0] - m0);
            s[nt][1] = __expf(s[nt][1] - m0);
            s[nt][2] = __expf(s[nt][2] - m1);
            s[nt][3] = __expf(s[nt][3] - m1);
            sum0 += s[nt][0] + s[nt][1];
            sum1 += s[nt][2] + s[nt][3];
        }
        sum0 += __shfl_xor_sync(FULL, sum0, 1);
        sum0 += __shfl_xor_sync(FULL, sum0, 2);
        sum1 += __shfl_xor_sync(FULL, sum1, 1);
        sum1 += __shfl_xor_sync(FULL, sum1, 2);
        l0 = l0 * al0 + sum0;
        l1 = l1 * al1 + sum1;

        // rescale O
#pragma unroll
        for (int nt = 0; nt < 4; nt++) {
            o[nt][0] *= al0; o[nt][1] *= al0;
            o[nt][2] *= al1; o[nt][3] *= al1;
        }

        // ---- P (fp16) @ V (hi/lo)  -> O (16x32 per warp) --------------------
#pragma unroll
        for (int kt = 0; kt < 4; kt++) {
            unsigned aP[4];
            aP[0] = pack_h2(s[2 * kt][0],     s[2 * kt][1]);
            aP[1] = pack_h2(s[2 * kt][2],     s[2 * kt][3]);
            aP[2] = pack_h2(s[2 * kt + 1][0], s[2 * kt + 1][1]);
            aP[3] = pack_h2(s[2 * kt + 1][2], s[2 * kt + 1][3]);
            int jbase = kt * 16 + lr * 2;
#pragma unroll
            for (int nt = 0; nt < 4; nt++) {
                int drow = nt * 8 + lq;
                unsigned vh0 = *reinterpret_cast<const unsigned*>(&SM[SM_VH + drow * VPITCH + jbase]);
                unsigned vh1 = *reinterpret_cast<const unsigned*>(&SM[SM_VH + drow * VPITCH + jbase + 8]);
                unsigned vl0 = *reinterpret_cast<const unsigned*>(&SM[SM_VL + drow * VPITCH + jbase]);
                unsigned vl1 = *reinterpret_cast<const unsigned*>(&SM[SM_VL + drow * VPITCH + jbase + 8]);
                mma16816(o[nt], aP, vh0, vh1);
                mma16816(o[nt], aP, vl0, vl1);
            }
        }
        __syncthreads();
    }

    // ---- Epilogue: divide by l, transpose via smem, coalesced store --------
    float inv0 = 1.0f / l0, inv1 = 1.0f / l1;
    {
        int r0 = wid * 16 + lq;
#pragma unroll
        for (int nt = 0; nt < 4; nt++) {
            int d = nt * 8 + lr * 2;
            SMf[r0 * QPITCH + d]           = o[nt][0] * inv0;
            SMf[r0 * QPITCH + d + 1]       = o[nt][1] * inv0;
            SMf[(r0 + 8) * QPITCH + d]     = o[nt][2] * inv1;
            SMf[(r0 + 8) * QPITCH + d + 1] = o[nt][3] * inv1;
        }
    }
    __syncthreads();
    float* ob = g_attn + ((size_t)b * HID_ + h * DHEAD_) * N_ + i0;
#pragma unroll
    for (int t = 0; t < 16; t++) {
        int idx = tid + t * 256;            // 4096 elements
        int d = idx >> 7, i = idx & 127;
        ob[(size_t)d * N_ + i] = SMf[i * QPITCH + d];
    }
}

// ---------------------------------------------------------------------------
extern "C" void kernel_launch(void* const* d_in, const int* in_sizes, int n_in,
                              void* d_out, int out_size) {
    const float* x     = (const float*)d_in[0];
    const float* g     = (const float*)d_in[1];
    const float* beta  = (const float*)d_in[2];
    const float* w_qkv = (const float*)d_in[3];
    const float* w_out = (const float*)d_in[4];
    const float* b_out = (const float*)d_in[5];
    float* out = (float*)d_out;

    float* qkv_ptr;  cudaGetSymbolAddress((void**)&qkv_ptr,  g_qkv);
    float* attn_ptr; cudaGetSymbolAddress((void**)&attn_ptr, g_attn);

    ln_stats_kernel<<<(B_ * N_) / 256, 256>>>(x);

    dim3 g2(N_ / 64, OQKV_ / 64, B_);
    gemm_kernel<OQKV_, true, true, false><<<g2, 256>>>(w_qkv, x, qkv_ptr, g, beta, nullptr);

    dim3 g3(N_ / 128, B_ * HEADS_);
    attn_mma_kernel<<<g3, 256>>>();

    dim3 g4(N_ / 64, HID_ / 64, B_);
    gemm_kernel<HID_, false, false, true><<<g4, 256>>>(w_out, attn_ptr, out, nullptr, nullptr, b_out);
}